// round 1
// baseline (speedup 1.0000x reference)
#include <cuda_runtime.h>

#define NN 50000
#define NE 640000
#define H 128
#define NL 4
#define NRBF 50
#define NG 64
#define LN_EPS 1e-5f
#define RBF_STEP (4.0f / 49.0f)
#define RBF_COEFF (-75.03125f)   // -0.5 / (4/49)^2

#define EPW 4   // edges per warp

// ---------------- device scratch (no allocation allowed) ----------------
__device__ float g_h[NN * H];     // node features
__device__ float g_xl[NN * H];    // h @ lw + lb
__device__ float g_agg[NN * H];   // segment-sum accumulator
__device__ float g_pool[NG * H];
__device__ float g_cnt[NG];

// ---------------- init: h = emb[x]; agg = 0; pool/cnt = 0 ----------------
__global__ void k_init(const int* __restrict__ x, const float* __restrict__ emb) {
    int gid = blockIdx.x * blockDim.x + threadIdx.x;
    int node = gid >> 5, lane = gid & 31;
    if (node < NN) {
        int xi = x[node];
        float4 v = ((const float4*)(emb + (size_t)xi * H))[lane];
        ((float4*)(g_h + (size_t)node * H))[lane] = v;
        float4 z = make_float4(0.f, 0.f, 0.f, 0.f);
        ((float4*)(g_agg + (size_t)node * H))[lane] = z;
    }
    if (gid < NG * H) g_pool[gid] = 0.f;
    if (gid < NG) g_cnt[gid] = 0.f;
}

// ---------------- xl = h @ lw + lb  (warp-per-node, shuffle broadcast) ----------------
__global__ void k_xl(const float* __restrict__ lw, const float* __restrict__ lb) {
    extern __shared__ float s[];
    float* lws = s;            // H*H
    float* lbs = s + H * H;    // H
    int tid = threadIdx.x;
    for (int i = tid; i < H * H / 4; i += blockDim.x)
        ((float4*)lws)[i] = ((const float4*)lw)[i];
    if (tid < H) lbs[tid] = lb[tid];
    __syncthreads();

    int warp = tid >> 5, lane = tid & 31;
    int wpb = blockDim.x >> 5;
    int nwarps = wpb * gridDim.x;
    for (int node = blockIdx.x * wpb + warp; node < NN; node += nwarps) {
        float4 hv = ((const float4*)(g_h + (size_t)node * H))[lane];
        float a0 = lbs[lane], a1 = lbs[lane + 32], a2 = lbs[lane + 64], a3 = lbs[lane + 96];
        #pragma unroll 8
        for (int sl = 0; sl < 32; sl++) {
            float b0 = __shfl_sync(0xffffffffu, hv.x, sl);
            float b1 = __shfl_sync(0xffffffffu, hv.y, sl);
            float b2 = __shfl_sync(0xffffffffu, hv.z, sl);
            float b3 = __shfl_sync(0xffffffffu, hv.w, sl);
            const float* wr = lws + (sl * 4) * H;
            a0 += b0 * wr[lane];           a1 += b0 * wr[lane + 32];
            a2 += b0 * wr[lane + 64];      a3 += b0 * wr[lane + 96];
            a0 += b1 * wr[H + lane];       a1 += b1 * wr[H + lane + 32];
            a2 += b1 * wr[H + lane + 64];  a3 += b1 * wr[H + lane + 96];
            a0 += b2 * wr[2*H + lane];     a1 += b2 * wr[2*H + lane + 32];
            a2 += b2 * wr[2*H + lane + 64];a3 += b2 * wr[2*H + lane + 96];
            a0 += b3 * wr[3*H + lane];     a1 += b3 * wr[3*H + lane + 32];
            a2 += b3 * wr[3*H + lane + 64];a3 += b3 * wr[3*H + lane + 96];
        }
        float* op = g_xl + (size_t)node * H;
        op[lane] = a0; op[lane + 32] = a1; op[lane + 64] = a2; op[lane + 96] = a3;
    }
}

// ---------------- fused edge kernel: rbf -> GEMV1 -> relu -> GEMV2 -> gather*mul -> atomic scatter ----------------
__global__ void k_edge(const int* __restrict__ erow, const int* __restrict__ ecol,
                       const float* __restrict__ eattr,
                       const float* __restrict__ fw1, const float* __restrict__ fb1,
                       const float* __restrict__ fw2, const float* __restrict__ fb2) {
    extern __shared__ float s[];
    float* fw1s = s;                               // NRBF*H   = 6400
    float* fw2s = fw1s + NRBF * H;                 // H*H      = 16384
    float* fb1s = fw2s + H * H;                    // 128
    float* fb2s = fb1s + H;                        // 128
    float* rbfs = fb2s + H;                        // 16*EPW*NRBF = 3200
    float* h1s  = rbfs + 16 * EPW * NRBF;          // 16*EPW*H    = 8192

    int tid = threadIdx.x;
    for (int i = tid; i < NRBF * H / 4; i += blockDim.x)
        ((float4*)fw1s)[i] = ((const float4*)fw1)[i];
    for (int i = tid; i < H * H / 4; i += blockDim.x)
        ((float4*)fw2s)[i] = ((const float4*)fw2)[i];
    if (tid < H) { fb1s[tid] = fb1[tid]; fb2s[tid] = fb2[tid]; }
    __syncthreads();

    int warp = tid >> 5, lane = tid & 31;
    float* my_rbf = rbfs + warp * EPW * NRBF;
    float* my_h1  = h1s  + warp * EPW * H;
    int gw = blockIdx.x * (blockDim.x >> 5) + warp;
    int nwarps = gridDim.x * (blockDim.x >> 5);
    int stride = nwarps * EPW;

    for (int e0 = gw * EPW; e0 < NE; e0 += stride) {
        // ---- RBF (each lane computes r = lane and r = lane+32) ----
        #pragma unroll
        for (int t = 0; t < EPW; t++) {
            int e = e0 + t;
            float d = eattr[e < NE ? e : NE - 1];
            float dd = d - (float)lane * RBF_STEP;
            my_rbf[t * NRBF + lane < EPW * NRBF ? t * NRBF + lane : 0] = 0.f; // dummy keep compiler honest
            if (lane < NRBF)
                my_rbf[t * NRBF + lane] = __expf(RBF_COEFF * dd * dd);
            int r2 = lane + 32;
            if (r2 < NRBF) {
                float dd2 = d - (float)r2 * RBF_STEP;
                my_rbf[t * NRBF + r2] = __expf(RBF_COEFF * dd2 * dd2);
            }
        }
        __syncwarp();

        // ---- GEMV1: h1 = relu(rbf @ fw1 + fb1) ----
        float acc[EPW][4];
        #pragma unroll
        for (int t = 0; t < EPW; t++) {
            acc[t][0] = fb1s[lane];       acc[t][1] = fb1s[lane + 32];
            acc[t][2] = fb1s[lane + 64];  acc[t][3] = fb1s[lane + 96];
        }
        #pragma unroll 2
        for (int r = 0; r < NRBF; r++) {
            float w0 = fw1s[r * H + lane];
            float w1 = fw1s[r * H + lane + 32];
            float w2 = fw1s[r * H + lane + 64];
            float w3 = fw1s[r * H + lane + 96];
            #pragma unroll
            for (int t = 0; t < EPW; t++) {
                float rb = my_rbf[t * NRBF + r];
                acc[t][0] += rb * w0; acc[t][1] += rb * w1;
                acc[t][2] += rb * w2; acc[t][3] += rb * w3;
            }
        }
        #pragma unroll
        for (int t = 0; t < EPW; t++) {
            my_h1[t * H + lane]      = fmaxf(acc[t][0], 0.f);
            my_h1[t * H + lane + 32] = fmaxf(acc[t][1], 0.f);
            my_h1[t * H + lane + 64] = fmaxf(acc[t][2], 0.f);
            my_h1[t * H + lane + 96] = fmaxf(acc[t][3], 0.f);
        }
        __syncwarp();

        // ---- GEMV2: w = h1 @ fw2 + fb2 ----
        float wac[EPW][4];
        #pragma unroll
        for (int t = 0; t < EPW; t++) {
            wac[t][0] = fb2s[lane];       wac[t][1] = fb2s[lane + 32];
            wac[t][2] = fb2s[lane + 64];  wac[t][3] = fb2s[lane + 96];
        }
        #pragma unroll 2
        for (int j = 0; j < H; j++) {
            float w0 = fw2s[j * H + lane];
            float w1 = fw2s[j * H + lane + 32];
            float w2 = fw2s[j * H + lane + 64];
            float w3 = fw2s[j * H + lane + 96];
            #pragma unroll
            for (int t = 0; t < EPW; t++) {
                float hv = my_h1[t * H + j];
                wac[t][0] += hv * w0; wac[t][1] += hv * w1;
                wac[t][2] += hv * w2; wac[t][3] += hv * w3;
            }
        }

        // ---- gather xl[col], multiply, scatter-add to agg[row] ----
        #pragma unroll
        for (int t = 0; t < EPW; t++) {
            int e = e0 + t;
            if (e < NE) {
                int cn = ecol[e], rn = erow[e];
                const float* xp = g_xl + (size_t)cn * H;
                float* op = g_agg + (size_t)rn * H;
                atomicAdd(op + lane,      xp[lane]      * wac[t][0]);
                atomicAdd(op + lane + 32, xp[lane + 32] * wac[t][1]);
                atomicAdd(op + lane + 64, xp[lane + 64] * wac[t][2]);
                atomicAdd(op + lane + 96, xp[lane + 96] * wac[t][3]);
            }
        }
    }
}

// ---------------- LayerNorm(h + agg), then zero agg for next layer ----------------
__global__ void k_ln(const float* __restrict__ gam, const float* __restrict__ bet) {
    int gid = blockIdx.x * blockDim.x + threadIdx.x;
    int node = gid >> 5, lane = gid & 31;
    if (node >= NN) return;
    size_t base = (size_t)node * H;
    float v[4];
    #pragma unroll
    for (int c = 0; c < 4; c++) {
        int k = lane + 32 * c;
        v[c] = g_h[base + k] + g_agg[base + k];
    }
    float sum = v[0] + v[1] + v[2] + v[3];
    #pragma unroll
    for (int o = 16; o > 0; o >>= 1) sum += __shfl_xor_sync(0xffffffffu, sum, o);
    float mu = sum * (1.f / H);
    float vs = 0.f;
    #pragma unroll
    for (int c = 0; c < 4; c++) { float d = v[c] - mu; vs += d * d; }
    #pragma unroll
    for (int o = 16; o > 0; o >>= 1) vs += __shfl_xor_sync(0xffffffffu, vs, o);
    float rs = rsqrtf(vs * (1.f / H) + LN_EPS);
    #pragma unroll
    for (int c = 0; c < 4; c++) {
        int k = lane + 32 * c;
        g_h[base + k] = (v[c] - mu) * rs * gam[k] + bet[k];
        g_agg[base + k] = 0.f;
    }
}

// ---------------- global mean pool ----------------
__global__ void k_pool(const int* __restrict__ batch) {
    int gid = blockIdx.x * blockDim.x + threadIdx.x;
    int node = gid >> 5, lane = gid & 31;
    if (node >= NN) return;
    int bg = batch[node];
    size_t base = (size_t)node * H;
    #pragma unroll
    for (int c = 0; c < 4; c++) {
        int k = lane + 32 * c;
        atomicAdd(&g_pool[bg * H + k], g_h[base + k]);
    }
    if (lane == 0) atomicAdd(&g_cnt[bg], 1.f);
}

__global__ void k_div(float* __restrict__ out) {
    int i = blockIdx.x * blockDim.x + threadIdx.x;
    if (i < NG * H) out[i] = g_pool[i] / fmaxf(g_cnt[i / H], 1.f);
}

// ---------------- launch ----------------
extern "C" void kernel_launch(void* const* d_in, const int* in_sizes, int n_in,
                              void* d_out, int out_size) {
    const int*   x     = (const int*)d_in[0];
    const int*   ei    = (const int*)d_in[1];
    const float* ea    = (const float*)d_in[2];
    const int*   batch = (const int*)d_in[3];
    const float* emb   = (const float*)d_in[4];
    const float* fw1   = (const float*)d_in[5];
    const float* fb1   = (const float*)d_in[6];
    const float* fw2   = (const float*)d_in[7];
    const float* fb2   = (const float*)d_in[8];
    const float* lw    = (const float*)d_in[9];
    const float* lb    = (const float*)d_in[10];
    const float* lng   = (const float*)d_in[11];
    const float* lnb   = (const float*)d_in[12];
    float* out = (float*)d_out;

    const int XL_SMEM   = (H * H + H) * sizeof(float);                 // 66 KB
    const int EDGE_SMEM = (NRBF * H + H * H + 2 * H + 16 * EPW * NRBF
                           + 16 * EPW * H) * sizeof(float);            // ~137.7 KB
    cudaFuncSetAttribute(k_xl,   cudaFuncAttributeMaxDynamicSharedMemorySize, XL_SMEM);
    cudaFuncSetAttribute(k_edge, cudaFuncAttributeMaxDynamicSharedMemorySize, EDGE_SMEM);

    int node_blocks = (NN * 32 + 255) / 256;

    k_init<<<node_blocks, 256>>>(x, emb);
    for (int i = 0; i < NL; i++) {
        k_xl<<<592, 256, XL_SMEM>>>(lw + (size_t)i * H * H, lb + (size_t)i * H);
        k_edge<<<148, 512, EDGE_SMEM>>>(ei, ei + NE, ea,
                                        fw1 + (size_t)i * NRBF * H, fb1 + (size_t)i * H,
                                        fw2 + (size_t)i * H * H,    fb2 + (size_t)i * H);
        k_ln<<<node_blocks, 256>>>(lng + (size_t)i * H, lnb + (size_t)i * H);
    }
    k_pool<<<node_blocks, 256>>>(batch);
    k_div<<<(NG * H + 255) / 256, 256>>>(out);
}

// round 2
// speedup vs baseline: 1.7507x; 1.7507x over previous
#include <cuda_runtime.h>

#define NN 50000
#define NE 640000
#define H 128
#define NL 4
#define NRBF 50
#define NG 64
#define LN_EPS 1e-5f
#define RBF_STEP (4.0f / 49.0f)
#define RBF_COEFF (-75.03125f)   // -0.5 / (4/49)^2

#define EPW 8      // edges per warp
#define NPAIR 4    // EPW/2

// ---------------- f32x2 helpers ----------------
union F2U { float2 f; unsigned long long u; };

__device__ __forceinline__ unsigned long long ffma2(unsigned long long a,
                                                    unsigned long long b,
                                                    unsigned long long c) {
    unsigned long long d;
    asm("fma.rn.f32x2 %0, %1, %2, %3;" : "=l"(d) : "l"(a), "l"(b), "l"(c));
    return d;
}
__device__ __forceinline__ unsigned long long dup2(float v) {
    unsigned long long d;
    asm("mov.b64 %0, {%1, %1};" : "=l"(d) : "f"(v));
    return d;
}
__device__ __forceinline__ void red2(float* p, float x, float y) {
    asm volatile("red.global.add.v2.f32 [%0], {%1, %2};"
                 :: "l"(p), "f"(x), "f"(y) : "memory");
}

// ---------------- device scratch ----------------
__device__ float g_h[NN * H];
__device__ float g_xl[NN * H];
__device__ float g_agg[NN * H];
__device__ float g_pool[NG * H];
__device__ float g_cnt[NG];

// ---------------- init: h = emb[x]; agg = 0; pool/cnt = 0 ----------------
__global__ void k_init(const int* __restrict__ x, const float* __restrict__ emb) {
    int gid = blockIdx.x * blockDim.x + threadIdx.x;
    int node = gid >> 5, lane = gid & 31;
    if (node < NN) {
        int xi = x[node];
        float4 v = ((const float4*)(emb + (size_t)xi * H))[lane];
        ((float4*)(g_h + (size_t)node * H))[lane] = v;
        ((float4*)(g_agg + (size_t)node * H))[lane] = make_float4(0.f, 0.f, 0.f, 0.f);
    }
    if (gid < NG * H) g_pool[gid] = 0.f;
    if (gid < NG) g_cnt[gid] = 0.f;
}

// ---------------- xl = h @ lw + lb  (4 nodes per warp, f32x2 node-pair packed) ----------------
__global__ __launch_bounds__(256, 1) void k_xl(const float* __restrict__ lw,
                                               const float* __restrict__ lb) {
    extern __shared__ float s[];
    float* lws = s;                 // H*H
    float* lbs = s + H * H;         // H
    float2* hs = (float2*)(s + H * H + H);  // 8 warps * 2 pairs * H float2

    int tid = threadIdx.x;
    for (int i = tid; i < H * H / 4; i += blockDim.x)
        ((float4*)lws)[i] = ((const float4*)lw)[i];
    if (tid < H) lbs[tid] = lb[tid];
    __syncthreads();

    int warp = tid >> 5, lane = tid & 31;
    float2* hs_w = hs + warp * 2 * H;
    int wpb = blockDim.x >> 5;
    int nwarps = wpb * gridDim.x;
    int gw = blockIdx.x * wpb + warp;

    // bias dup regs (channels lane+32g for both nodes of a pair)
    unsigned long long bia[4];
    #pragma unroll
    for (int g = 0; g < 4; g++) bia[g] = dup2(lbs[lane + 32 * g]);

    for (int n0 = gw * 4; n0 < NN; n0 += nwarps * 4) {
        // stage h for 2 node-pairs, interleaved
        #pragma unroll
        for (int q = 0; q < 2; q++) {
            int nA = n0 + 2 * q, nB = nA + 1;
            const float* ha = g_h + (size_t)nA * H;
            const float* hb = g_h + (size_t)nB * H;
            #pragma unroll
            for (int g = 0; g < 4; g++) {
                int k = lane + 32 * g;
                hs_w[q * H + k] = make_float2(ha[k], hb[k]);
            }
        }
        __syncwarp();

        unsigned long long acc[2][4];
        #pragma unroll
        for (int q = 0; q < 2; q++)
            #pragma unroll
            for (int g = 0; g < 4; g++) acc[q][g] = bia[g];

        #pragma unroll 4
        for (int k = 0; k < H; k++) {
            const float* wr = lws + k * H;
            unsigned long long d0 = dup2(wr[lane]);
            unsigned long long d1 = dup2(wr[lane + 32]);
            unsigned long long d2 = dup2(wr[lane + 64]);
            unsigned long long d3 = dup2(wr[lane + 96]);
            #pragma unroll
            for (int q = 0; q < 2; q++) {
                F2U hv; hv.f = hs_w[q * H + k];      // broadcast LDS.64
                acc[q][0] = ffma2(hv.u, d0, acc[q][0]);
                acc[q][1] = ffma2(hv.u, d1, acc[q][1]);
                acc[q][2] = ffma2(hv.u, d2, acc[q][2]);
                acc[q][3] = ffma2(hv.u, d3, acc[q][3]);
            }
        }

        #pragma unroll
        for (int q = 0; q < 2; q++) {
            int nA = n0 + 2 * q, nB = nA + 1;
            float* oa = g_xl + (size_t)nA * H;
            float* ob = g_xl + (size_t)nB * H;
            #pragma unroll
            for (int g = 0; g < 4; g++) {
                F2U u; u.u = acc[q][g];
                oa[lane + 32 * g] = u.f.x;
                ob[lane + 32 * g] = u.f.y;
            }
        }
        __syncwarp();
    }
}

// ---------------- fused edge kernel (f32x2 edge-pair packed) ----------------
// smem float layout:
//   fw1s [0,6400)  fw2s [6400,22784)  fb1s [22784,22912)  fb2s [22912,23040)
//   rbfp (float2)  [23040 floats)  : 16 warps * NPAIR * NRBF f2  = 6400 floats
//   h1p  (float2)  [29440 floats)  : 16 warps * NPAIR * H    f2  = 16384 floats
__global__ __launch_bounds__(512, 1) void k_edge(
        const int* __restrict__ erow, const int* __restrict__ ecol,
        const float* __restrict__ eattr,
        const float* __restrict__ fw1, const float* __restrict__ fb1,
        const float* __restrict__ fw2, const float* __restrict__ fb2) {
    extern __shared__ float s[];
    float* fw1s = s;
    float* fw2s = s + NRBF * H;
    float* fb1s = fw2s + H * H;
    float* fb2s = fb1s + H;
    float2* rbfp = (float2*)(fb2s + H);
    float2* h1p  = rbfp + 16 * NPAIR * NRBF;

    int tid = threadIdx.x;
    for (int i = tid; i < NRBF * H / 4; i += blockDim.x)
        ((float4*)fw1s)[i] = ((const float4*)fw1)[i];
    for (int i = tid; i < H * H / 4; i += blockDim.x)
        ((float4*)fw2s)[i] = ((const float4*)fw2)[i];
    if (tid < H) { fb1s[tid] = fb1[tid]; fb2s[tid] = fb2[tid]; }
    __syncthreads();

    int warp = tid >> 5, lane = tid & 31;
    float2* my_rbf = rbfp + warp * NPAIR * NRBF;
    float2* my_h1  = h1p  + warp * NPAIR * H;
    int gw = blockIdx.x * (blockDim.x >> 5) + warp;
    int nwarps = gridDim.x * (blockDim.x >> 5);
    int stride = nwarps * EPW;

    // bias dup regs: channels (2l, 2l+1, 64+2l, 65+2l)
    float2 b1a = ((const float2*)fb1s)[lane];
    float2 b1b = ((const float2*)(fb1s + 64))[lane];
    float2 b2a = ((const float2*)fb2s)[lane];
    float2 b2b = ((const float2*)(fb2s + 64))[lane];
    unsigned long long bi1[4] = { dup2(b1a.x), dup2(b1a.y), dup2(b1b.x), dup2(b1b.y) };
    unsigned long long bi2[4] = { dup2(b2a.x), dup2(b2a.y), dup2(b2b.x), dup2(b2b.y) };

    for (int e0 = gw * EPW; e0 < NE; e0 += stride) {   // NE % EPW == 0: all groups full
        int pbase = e0 >> 1;   // pair index

        // ---- RBF: pair-interleaved (edge even, edge odd) ----
        #pragma unroll
        for (int p = 0; p < NPAIR; p++) {
            float2 dd = ((const float2*)eattr)[pbase + p];
            if (lane < NRBF) {
                float o = (float)lane * RBF_STEP;
                float u0 = dd.x - o, u1 = dd.y - o;
                my_rbf[p * NRBF + lane] =
                    make_float2(__expf(RBF_COEFF * u0 * u0), __expf(RBF_COEFF * u1 * u1));
            }
            int r2 = lane + 32;
            if (r2 < NRBF) {
                float o = (float)r2 * RBF_STEP;
                float u0 = dd.x - o, u1 = dd.y - o;
                my_rbf[p * NRBF + r2] =
                    make_float2(__expf(RBF_COEFF * u0 * u0), __expf(RBF_COEFF * u1 * u1));
            }
        }
        __syncwarp();

        // ---- GEMV1: h1 = relu(rbf @ fw1 + fb1) ----
        unsigned long long acc[NPAIR][4];
        #pragma unroll
        for (int p = 0; p < NPAIR; p++)
            #pragma unroll
            for (int g = 0; g < 4; g++) acc[p][g] = bi1[g];

        #pragma unroll 2
        for (int r = 0; r < NRBF; r++) {
            float2 wa = ((const float2*)(fw1s + r * H))[lane];
            float2 wb = ((const float2*)(fw1s + r * H + 64))[lane];
            unsigned long long d0 = dup2(wa.x), d1 = dup2(wa.y);
            unsigned long long d2 = dup2(wb.x), d3 = dup2(wb.y);
            #pragma unroll
            for (int p = 0; p < NPAIR; p++) {
                F2U rb; rb.f = my_rbf[p * NRBF + r];   // LDS.64 broadcast
                acc[p][0] = ffma2(rb.u, d0, acc[p][0]);
                acc[p][1] = ffma2(rb.u, d1, acc[p][1]);
                acc[p][2] = ffma2(rb.u, d2, acc[p][2]);
                acc[p][3] = ffma2(rb.u, d3, acc[p][3]);
            }
        }
        // relu + store pair-interleaved h1
        #pragma unroll
        for (int p = 0; p < NPAIR; p++) {
            F2U u0, u1, u2, u3;
            u0.u = acc[p][0]; u1.u = acc[p][1]; u2.u = acc[p][2]; u3.u = acc[p][3];
            u0.f.x = fmaxf(u0.f.x, 0.f); u0.f.y = fmaxf(u0.f.y, 0.f);
            u1.f.x = fmaxf(u1.f.x, 0.f); u1.f.y = fmaxf(u1.f.y, 0.f);
            u2.f.x = fmaxf(u2.f.x, 0.f); u2.f.y = fmaxf(u2.f.y, 0.f);
            u3.f.x = fmaxf(u3.f.x, 0.f); u3.f.y = fmaxf(u3.f.y, 0.f);
            my_h1[p * H + 2 * lane]      = u0.f;
            my_h1[p * H + 2 * lane + 1]  = u1.f;
            my_h1[p * H + 64 + 2 * lane] = u2.f;
            my_h1[p * H + 65 + 2 * lane] = u3.f;
        }
        __syncwarp();

        // ---- GEMV2: w = h1 @ fw2 + fb2 ----
        #pragma unroll
        for (int p = 0; p < NPAIR; p++)
            #pragma unroll
            for (int g = 0; g < 4; g++) acc[p][g] = bi2[g];

        #pragma unroll 4
        for (int j = 0; j < H; j++) {
            float2 wa = ((const float2*)(fw2s + j * H))[lane];
            float2 wb = ((const float2*)(fw2s + j * H + 64))[lane];
            unsigned long long d0 = dup2(wa.x), d1 = dup2(wa.y);
            unsigned long long d2 = dup2(wb.x), d3 = dup2(wb.y);
            #pragma unroll
            for (int p = 0; p < NPAIR; p++) {
                F2U hv; hv.f = my_h1[p * H + j];      // LDS.64 broadcast
                acc[p][0] = ffma2(hv.u, d0, acc[p][0]);
                acc[p][1] = ffma2(hv.u, d1, acc[p][1]);
                acc[p][2] = ffma2(hv.u, d2, acc[p][2]);
                acc[p][3] = ffma2(hv.u, d3, acc[p][3]);
            }
        }

        // ---- gather xl[col] * w, vector-reduce into agg[row] ----
        #pragma unroll
        for (int p = 0; p < NPAIR; p++) {
            int2 c2 = ((const int2*)ecol)[pbase + p];
            int2 r2 = ((const int2*)erow)[pbase + p];
            F2U a0, a1, a2, a3;
            a0.u = acc[p][0]; a1.u = acc[p][1]; a2.u = acc[p][2]; a3.u = acc[p][3];

            {   // even edge (lo halves)
                const float* xp = g_xl + (size_t)c2.x * H;
                float2 xa = *(const float2*)(xp + 2 * lane);
                float2 xb = *(const float2*)(xp + 64 + 2 * lane);
                float* op = g_agg + (size_t)r2.x * H;
                red2(op + 2 * lane,      xa.x * a0.f.x, xa.y * a1.f.x);
                red2(op + 64 + 2 * lane, xb.x * a2.f.x, xb.y * a3.f.x);
            }
            {   // odd edge (hi halves)
                const float* xp = g_xl + (size_t)c2.y * H;
                float2 xa = *(const float2*)(xp + 2 * lane);
                float2 xb = *(const float2*)(xp + 64 + 2 * lane);
                float* op = g_agg + (size_t)r2.y * H;
                red2(op + 2 * lane,      xa.x * a0.f.y, xa.y * a1.f.y);
                red2(op + 64 + 2 * lane, xb.x * a2.f.y, xb.y * a3.f.y);
            }
        }
    }
}

// ---------------- LayerNorm(h + agg), then zero agg ----------------
__global__ void k_ln(const float* __restrict__ gam, const float* __restrict__ bet) {
    int gid = blockIdx.x * blockDim.x + threadIdx.x;
    int node = gid >> 5, lane = gid & 31;
    if (node >= NN) return;
    size_t base = (size_t)node * H;
    float v[4];
    #pragma unroll
    for (int c = 0; c < 4; c++) {
        int k = lane + 32 * c;
        v[c] = g_h[base + k] + g_agg[base + k];
    }
    float sum = v[0] + v[1] + v[2] + v[3];
    #pragma unroll
    for (int o = 16; o > 0; o >>= 1) sum += __shfl_xor_sync(0xffffffffu, sum, o);
    float mu = sum * (1.f / H);
    float vs = 0.f;
    #pragma unroll
    for (int c = 0; c < 4; c++) { float d = v[c] - mu; vs += d * d; }
    #pragma unroll
    for (int o = 16; o > 0; o >>= 1) vs += __shfl_xor_sync(0xffffffffu, vs, o);
    float rs = rsqrtf(vs * (1.f / H) + LN_EPS);
    #pragma unroll
    for (int c = 0; c < 4; c++) {
        int k = lane + 32 * c;
        g_h[base + k] = (v[c] - mu) * rs * gam[k] + bet[k];
        g_agg[base + k] = 0.f;
    }
}

// ---------------- global mean pool ----------------
__global__ void k_pool(const int* __restrict__ batch) {
    int gid = blockIdx.x * blockDim.x + threadIdx.x;
    int node = gid >> 5, lane = gid & 31;
    if (node >= NN) return;
    int bg = batch[node];
    size_t base = (size_t)node * H;
    #pragma unroll
    for (int c = 0; c < 4; c++) {
        int k = lane + 32 * c;
        atomicAdd(&g_pool[bg * H + k], g_h[base + k]);
    }
    if (lane == 0) atomicAdd(&g_cnt[bg], 1.f);
}

__global__ void k_div(float* __restrict__ out) {
    int i = blockIdx.x * blockDim.x + threadIdx.x;
    if (i < NG * H) out[i] = g_pool[i] / fmaxf(g_cnt[i / H], 1.f);
}

// ---------------- launch ----------------
extern "C" void kernel_launch(void* const* d_in, const int* in_sizes, int n_in,
                              void* d_out, int out_size) {
    const int*   x     = (const int*)d_in[0];
    const int*   ei    = (const int*)d_in[1];
    const float* ea    = (const float*)d_in[2];
    const int*   batch = (const int*)d_in[3];
    const float* emb   = (const float*)d_in[4];
    const float* fw1   = (const float*)d_in[5];
    const float* fb1   = (const float*)d_in[6];
    const float* fw2   = (const float*)d_in[7];
    const float* fb2   = (const float*)d_in[8];
    const float* lw    = (const float*)d_in[9];
    const float* lb    = (const float*)d_in[10];
    const float* lng   = (const float*)d_in[11];
    const float* lnb   = (const float*)d_in[12];
    float* out = (float*)d_out;

    const int XL_SMEM = (H * H + H) * sizeof(float) + 8 * 2 * H * sizeof(float2); // ~82 KB
    const int EDGE_SMEM = (NRBF * H + H * H + 2 * H) * sizeof(float)
                        + 16 * NPAIR * NRBF * sizeof(float2)
                        + 16 * NPAIR * H * sizeof(float2);                        // ~179 KB
    cudaFuncSetAttribute(k_xl,   cudaFuncAttributeMaxDynamicSharedMemorySize, XL_SMEM);
    cudaFuncSetAttribute(k_edge, cudaFuncAttributeMaxDynamicSharedMemorySize, EDGE_SMEM);

    int node_blocks = (NN * 32 + 255) / 256;

    k_init<<<node_blocks, 256>>>(x, emb);
    for (int i = 0; i < NL; i++) {
        k_xl<<<148, 256, XL_SMEM>>>(lw + (size_t)i * H * H, lb + (size_t)i * H);
        k_edge<<<148, 512, EDGE_SMEM>>>(ei, ei + NE, ea,
                                        fw1 + (size_t)i * NRBF * H, fb1 + (size_t)i * H,
                                        fw2 + (size_t)i * H * H,    fb2 + (size_t)i * H);
        k_ln<<<node_blocks, 256>>>(lng + (size_t)i * H, lnb + (size_t)i * H);
    }
    k_pool<<<node_blocks, 256>>>(batch);
    k_div<<<(NG * H + 255) / 256, 256>>>(out);
}

// round 3
// speedup vs baseline: 4.5382x; 2.5922x over previous
#include <cuda_runtime.h>

#define NN 50000
#define NE 640000
#define H 128
#define NL 4
#define NRBF 50
#define NG 64
#define LN_EPS 1e-5f
#define RBF_STEP (4.0f / 49.0f)
#define RBF_COEFF (-75.03125f)   // -0.5 / (4/49)^2

#define T_TAB 16384
#define TAB_STEP (4.0f / (T_TAB - 1))
#define TAB_INV ((float)(T_TAB - 1) / 4.0f)

// ---------------- f32x2 helpers ----------------
union F2U { float2 f; unsigned long long u; };

__device__ __forceinline__ unsigned long long ffma2(unsigned long long a,
                                                    unsigned long long b,
                                                    unsigned long long c) {
    unsigned long long d;
    asm("fma.rn.f32x2 %0, %1, %2, %3;" : "=l"(d) : "l"(a), "l"(b), "l"(c));
    return d;
}
__device__ __forceinline__ unsigned long long dup2(float v) {
    unsigned long long d;
    asm("mov.b64 %0, {%1, %1};" : "=l"(d) : "f"(v));
    return d;
}
__device__ __forceinline__ void red2(float* p, float x, float y) {
    asm volatile("red.global.add.v2.f32 [%0], {%1, %2};"
                 :: "l"(p), "f"(x), "f"(y) : "memory");
}

// ---------------- device scratch ----------------
__device__ float g_h[NN * H];
__device__ float g_xl[NN * H];
__device__ float g_agg[NN * H];
__device__ float g_tab[T_TAB * H];   // filter table for current layer (8 MB)
__device__ float g_pool[NG * H];
__device__ float g_cnt[NG];

// ---------------- init: h = emb[x]; agg = 0; pool/cnt = 0 ----------------
__global__ void k_init(const int* __restrict__ x, const float* __restrict__ emb) {
    int gid = blockIdx.x * blockDim.x + threadIdx.x;
    int node = gid >> 5, lane = gid & 31;
    if (node < NN) {
        int xi = x[node];
        float4 v = ((const float4*)(emb + (size_t)xi * H))[lane];
        ((float4*)(g_h + (size_t)node * H))[lane] = v;
        ((float4*)(g_agg + (size_t)node * H))[lane] = make_float4(0.f, 0.f, 0.f, 0.f);
    }
    if (gid < NG * H) g_pool[gid] = 0.f;
    if (gid < NG) g_cnt[gid] = 0.f;
}

// ---------------- xl = h @ lw + lb  (4 nodes per warp, f32x2 node-pair packed) ----------------
__global__ __launch_bounds__(256, 1) void k_xl(const float* __restrict__ lw,
                                               const float* __restrict__ lb) {
    extern __shared__ float s[];
    float* lws = s;                 // H*H
    float* lbs = s + H * H;         // H
    float2* hs = (float2*)(s + H * H + H);  // 8 warps * 2 pairs * H float2

    int tid = threadIdx.x;
    for (int i = tid; i < H * H / 4; i += blockDim.x)
        ((float4*)lws)[i] = ((const float4*)lw)[i];
    if (tid < H) lbs[tid] = lb[tid];
    __syncthreads();

    int warp = tid >> 5, lane = tid & 31;
    float2* hs_w = hs + warp * 2 * H;
    int wpb = blockDim.x >> 5;
    int nwarps = wpb * gridDim.x;
    int gw = blockIdx.x * wpb + warp;

    unsigned long long bia[4];
    #pragma unroll
    for (int g = 0; g < 4; g++) bia[g] = dup2(lbs[lane + 32 * g]);

    for (int n0 = gw * 4; n0 < NN; n0 += nwarps * 4) {
        #pragma unroll
        for (int q = 0; q < 2; q++) {
            int nA = n0 + 2 * q, nB = nA + 1;
            const float* ha = g_h + (size_t)nA * H;
            const float* hb = g_h + (size_t)nB * H;
            #pragma unroll
            for (int g = 0; g < 4; g++) {
                int k = lane + 32 * g;
                hs_w[q * H + k] = make_float2(ha[k], hb[k]);
            }
        }
        __syncwarp();

        unsigned long long acc[2][4];
        #pragma unroll
        for (int q = 0; q < 2; q++)
            #pragma unroll
            for (int g = 0; g < 4; g++) acc[q][g] = bia[g];

        #pragma unroll 4
        for (int k = 0; k < H; k++) {
            const float* wr = lws + k * H;
            unsigned long long d0 = dup2(wr[lane]);
            unsigned long long d1 = dup2(wr[lane + 32]);
            unsigned long long d2 = dup2(wr[lane + 64]);
            unsigned long long d3 = dup2(wr[lane + 96]);
            #pragma unroll
            for (int q = 0; q < 2; q++) {
                F2U hv; hv.f = hs_w[q * H + k];
                acc[q][0] = ffma2(hv.u, d0, acc[q][0]);
                acc[q][1] = ffma2(hv.u, d1, acc[q][1]);
                acc[q][2] = ffma2(hv.u, d2, acc[q][2]);
                acc[q][3] = ffma2(hv.u, d3, acc[q][3]);
            }
        }

        #pragma unroll
        for (int q = 0; q < 2; q++) {
            int nA = n0 + 2 * q, nB = nA + 1;
            float* oa = g_xl + (size_t)nA * H;
            float* ob = g_xl + (size_t)nB * H;
            #pragma unroll
            for (int g = 0; g < 4; g++) {
                F2U u; u.u = acc[q][g];
                oa[lane + 32 * g] = u.f.x;
                ob[lane + 32 * g] = u.f.y;
            }
        }
        __syncwarp();
    }
}

// ---------------- build filter table: W[t] = relu(rbf(d_t)@fw1+b1)@fw2+b2 ----------------
// warp per grid point; weights staged in SMEM.
__global__ __launch_bounds__(512, 1) void k_ftab(
        const float* __restrict__ fw1, const float* __restrict__ fb1,
        const float* __restrict__ fw2, const float* __restrict__ fb2) {
    extern __shared__ float s[];
    float* fw1s = s;                       // 6400
    float* fw2s = fw1s + NRBF * H;         // 16384
    float* fb1s = fw2s + H * H;            // 128
    float* fb2s = fb1s + H;                // 128
    float* rbfs = fb2s + H;                // 16 warps * 64
    float* h1s  = rbfs + 16 * 64;          // 16 warps * 128

    int tid = threadIdx.x;
    for (int i = tid; i < NRBF * H / 4; i += blockDim.x)
        ((float4*)fw1s)[i] = ((const float4*)fw1)[i];
    for (int i = tid; i < H * H / 4; i += blockDim.x)
        ((float4*)fw2s)[i] = ((const float4*)fw2)[i];
    if (tid < H) { fb1s[tid] = fb1[tid]; fb2s[tid] = fb2[tid]; }
    __syncthreads();

    int warp = tid >> 5, lane = tid & 31;
    float* rbfw = rbfs + warp * 64;
    float* h1w  = h1s  + warp * H;
    int gw = blockIdx.x * (blockDim.x >> 5) + warp;
    int nwarps = gridDim.x * (blockDim.x >> 5);

    for (int t = gw; t < T_TAB; t += nwarps) {
        float d = (float)t * TAB_STEP;
        if (lane < NRBF) {
            float u = d - (float)lane * RBF_STEP;
            rbfw[lane] = __expf(RBF_COEFF * u * u);
        }
        int r2 = lane + 32;
        if (r2 < NRBF) {
            float u = d - (float)r2 * RBF_STEP;
            rbfw[r2] = __expf(RBF_COEFF * u * u);
        }
        __syncwarp();

        float a0 = fb1s[lane], a1 = fb1s[lane + 32], a2 = fb1s[lane + 64], a3 = fb1s[lane + 96];
        #pragma unroll 5
        for (int r = 0; r < NRBF; r++) {
            float rb = rbfw[r];
            const float* wr = fw1s + r * H;
            a0 += rb * wr[lane];      a1 += rb * wr[lane + 32];
            a2 += rb * wr[lane + 64]; a3 += rb * wr[lane + 96];
        }
        h1w[lane]      = fmaxf(a0, 0.f);
        h1w[lane + 32] = fmaxf(a1, 0.f);
        h1w[lane + 64] = fmaxf(a2, 0.f);
        h1w[lane + 96] = fmaxf(a3, 0.f);
        __syncwarp();

        float b0 = fb2s[lane], b1 = fb2s[lane + 32], b2 = fb2s[lane + 64], b3 = fb2s[lane + 96];
        #pragma unroll 4
        for (int j = 0; j < H; j++) {
            float hv = h1w[j];
            const float* wr = fw2s + j * H;
            b0 += hv * wr[lane];      b1 += hv * wr[lane + 32];
            b2 += hv * wr[lane + 64]; b3 += hv * wr[lane + 96];
        }
        float* op = g_tab + (size_t)t * H;
        op[lane] = b0; op[lane + 32] = b1; op[lane + 64] = b2; op[lane + 96] = b3;
        __syncwarp();
    }
}

// ---------------- message kernel: msg = xl[col] * lerp(tab, d); red into agg[row] ----------------
#define MEPW 4
__global__ __launch_bounds__(256) void k_msg(const int* __restrict__ erow,
                                             const int* __restrict__ ecol,
                                             const float* __restrict__ eattr) {
    int tid = threadIdx.x;
    int warp = tid >> 5, lane = tid & 31;
    int gw = blockIdx.x * (blockDim.x >> 5) + warp;
    int nwarps = gridDim.x * (blockDim.x >> 5);
    const float4* tab4 = (const float4*)g_tab;
    const float4* xl4  = (const float4*)g_xl;

    for (int e0 = gw * MEPW; e0 < NE; e0 += nwarps * MEPW) {   // NE % MEPW == 0
        float4 w0[MEPW], w1[MEPW], xv[MEPW];
        int rn[MEPW];
        float tt[MEPW];
        #pragma unroll
        for (int t = 0; t < MEPW; t++) {
            int e = e0 + t;
            float f = __ldg(eattr + e) * TAB_INV;
            int i = (int)f;
            if (i > T_TAB - 2) i = T_TAB - 2;
            tt[t] = f - (float)i;
            int cn = __ldg(ecol + e);
            rn[t] = __ldg(erow + e);
            w0[t] = tab4[(size_t)i * 32 + lane];
            w1[t] = tab4[(size_t)i * 32 + 32 + lane];
            xv[t] = xl4[(size_t)cn * 32 + lane];
        }
        #pragma unroll
        for (int t = 0; t < MEPW; t++) {
            float u = tt[t];
            float wx = fmaf(u, w1[t].x - w0[t].x, w0[t].x);
            float wy = fmaf(u, w1[t].y - w0[t].y, w0[t].y);
            float wz = fmaf(u, w1[t].z - w0[t].z, w0[t].z);
            float ww = fmaf(u, w1[t].w - w0[t].w, w0[t].w);
            float* op = g_agg + (size_t)rn[t] * H + 4 * lane;
            red2(op,     xv[t].x * wx, xv[t].y * wy);
            red2(op + 2, xv[t].z * wz, xv[t].w * ww);
        }
    }
}

// ---------------- LayerNorm(h + agg), then zero agg ----------------
__global__ void k_ln(const float* __restrict__ gam, const float* __restrict__ bet) {
    int gid = blockIdx.x * blockDim.x + threadIdx.x;
    int node = gid >> 5, lane = gid & 31;
    if (node >= NN) return;
    size_t base = (size_t)node * H;
    float v[4];
    #pragma unroll
    for (int c = 0; c < 4; c++) {
        int k = lane + 32 * c;
        v[c] = g_h[base + k] + g_agg[base + k];
    }
    float sum = v[0] + v[1] + v[2] + v[3];
    #pragma unroll
    for (int o = 16; o > 0; o >>= 1) sum += __shfl_xor_sync(0xffffffffu, sum, o);
    float mu = sum * (1.f / H);
    float vs = 0.f;
    #pragma unroll
    for (int c = 0; c < 4; c++) { float d = v[c] - mu; vs += d * d; }
    #pragma unroll
    for (int o = 16; o > 0; o >>= 1) vs += __shfl_xor_sync(0xffffffffu, vs, o);
    float rs = rsqrtf(vs * (1.f / H) + LN_EPS);
    #pragma unroll
    for (int c = 0; c < 4; c++) {
        int k = lane + 32 * c;
        g_h[base + k] = (v[c] - mu) * rs * gam[k] + bet[k];
        g_agg[base + k] = 0.f;
    }
}

// ---------------- global mean pool ----------------
__global__ void k_pool(const int* __restrict__ batch) {
    int gid = blockIdx.x * blockDim.x + threadIdx.x;
    int node = gid >> 5, lane = gid & 31;
    if (node >= NN) return;
    int bg = batch[node];
    size_t base = (size_t)node * H;
    #pragma unroll
    for (int c = 0; c < 4; c++) {
        int k = lane + 32 * c;
        atomicAdd(&g_pool[bg * H + k], g_h[base + k]);
    }
    if (lane == 0) atomicAdd(&g_cnt[bg], 1.f);
}

__global__ void k_div(float* __restrict__ out) {
    int i = blockIdx.x * blockDim.x + threadIdx.x;
    if (i < NG * H) out[i] = g_pool[i] / fmaxf(g_cnt[i / H], 1.f);
}

// ---------------- launch ----------------
extern "C" void kernel_launch(void* const* d_in, const int* in_sizes, int n_in,
                              void* d_out, int out_size) {
    const int*   x     = (const int*)d_in[0];
    const int*   ei    = (const int*)d_in[1];
    const float* ea    = (const float*)d_in[2];
    const int*   batch = (const int*)d_in[3];
    const float* emb   = (const float*)d_in[4];
    const float* fw1   = (const float*)d_in[5];
    const float* fb1   = (const float*)d_in[6];
    const float* fw2   = (const float*)d_in[7];
    const float* fb2   = (const float*)d_in[8];
    const float* lw    = (const float*)d_in[9];
    const float* lb    = (const float*)d_in[10];
    const float* lng   = (const float*)d_in[11];
    const float* lnb   = (const float*)d_in[12];
    float* out = (float*)d_out;

    const int XL_SMEM = (H * H + H) * sizeof(float) + 8 * 2 * H * sizeof(float2); // ~82 KB
    const int FT_SMEM = (NRBF * H + H * H + 2 * H + 16 * 64 + 16 * H) * sizeof(float); // ~104 KB
    cudaFuncSetAttribute(k_xl,   cudaFuncAttributeMaxDynamicSharedMemorySize, XL_SMEM);
    cudaFuncSetAttribute(k_ftab, cudaFuncAttributeMaxDynamicSharedMemorySize, FT_SMEM);

    int node_blocks = (NN * 32 + 255) / 256;

    k_init<<<node_blocks, 256>>>(x, emb);
    for (int i = 0; i < NL; i++) {
        k_xl<<<148, 256, XL_SMEM>>>(lw + (size_t)i * H * H, lb + (size_t)i * H);
        k_ftab<<<148, 512, FT_SMEM>>>(fw1 + (size_t)i * NRBF * H, fb1 + (size_t)i * H,
                                      fw2 + (size_t)i * H * H,    fb2 + (size_t)i * H);
        k_msg<<<592, 256>>>(ei, ei + NE, ea);
        k_ln<<<node_blocks, 256>>>(lng + (size_t)i * H, lnb + (size_t)i * H);
    }
    k_pool<<<node_blocks, 256>>>(batch);
    k_div<<<(NG * H + 255) / 256, 256>>>(out);
}

// round 4
// speedup vs baseline: 5.1118x; 1.1264x over previous
#include <cuda_runtime.h>

#define NN 50000
#define NE 640000
#define H 128
#define NL 4
#define NRBF 50
#define NG 64
#define LN_EPS 1e-5f
#define RBF_STEP (4.0f / 49.0f)
#define RBF_COEFF (-75.03125f)   // -0.5 / (4/49)^2

#define T_TAB 16384
#define TAB_STEP (4.0f / (T_TAB - 1))
#define TAB_INV ((float)(T_TAB - 1) / 4.0f)

// ---------------- f32x2 helpers ----------------
union F2U { float2 f; unsigned long long u; };

__device__ __forceinline__ unsigned long long ffma2(unsigned long long a,
                                                    unsigned long long b,
                                                    unsigned long long c) {
    unsigned long long d;
    asm("fma.rn.f32x2 %0, %1, %2, %3;" : "=l"(d) : "l"(a), "l"(b), "l"(c));
    return d;
}
__device__ __forceinline__ unsigned long long dup2(float v) {
    unsigned long long d;
    asm("mov.b64 %0, {%1, %1};" : "=l"(d) : "f"(v));
    return d;
}
__device__ __forceinline__ void red2(float* p, float x, float y) {
    asm volatile("red.global.add.v2.f32 [%0], {%1, %2};"
                 :: "l"(p), "f"(x), "f"(y) : "memory");
}

// ---------------- device scratch ----------------
__device__ float g_h[NN * H];
__device__ float g_xl[NN * H];
__device__ float g_agg[NN * H];
__device__ float g_tab[T_TAB * H];   // filter table for current layer (8 MB)
__device__ float g_pool[NG * H];
__device__ float g_cnt[NG];

// ---------------- init: h = emb[x]; agg = 0; pool/cnt = 0 ----------------
__global__ void k_init(const int* __restrict__ x, const float* __restrict__ emb) {
    int gid = blockIdx.x * blockDim.x + threadIdx.x;
    int node = gid >> 5, lane = gid & 31;
    if (node < NN) {
        int xi = x[node];
        float4 v = ((const float4*)(emb + (size_t)xi * H))[lane];
        ((float4*)(g_h + (size_t)node * H))[lane] = v;
        ((float4*)(g_agg + (size_t)node * H))[lane] = make_float4(0.f, 0.f, 0.f, 0.f);
    }
    if (gid < NG * H) g_pool[gid] = 0.f;
    if (gid < NG) g_cnt[gid] = 0.f;
}

// ---------------- xl = h @ lw + lb  (4 nodes per warp, f32x2 node-pair packed) ----------------
__global__ __launch_bounds__(256) void k_xl(const float* __restrict__ lw,
                                            const float* __restrict__ lb) {
    extern __shared__ float s[];
    float* lws = s;                 // H*H
    float* lbs = s + H * H;         // H
    float2* hs = (float2*)(s + H * H + H);  // 8 warps * 2 pairs * H float2

    int tid = threadIdx.x;
    for (int i = tid; i < H * H / 4; i += blockDim.x)
        ((float4*)lws)[i] = ((const float4*)lw)[i];
    if (tid < H) lbs[tid] = lb[tid];
    __syncthreads();

    int warp = tid >> 5, lane = tid & 31;
    float2* hs_w = hs + warp * 2 * H;
    int wpb = blockDim.x >> 5;
    int nwarps = wpb * gridDim.x;
    int gw = blockIdx.x * wpb + warp;

    unsigned long long bia[4];
    #pragma unroll
    for (int g = 0; g < 4; g++) bia[g] = dup2(lbs[lane + 32 * g]);

    for (int n0 = gw * 4; n0 < NN; n0 += nwarps * 4) {   // NN % 4 == 0
        #pragma unroll
        for (int q = 0; q < 2; q++) {
            int nA = n0 + 2 * q, nB = nA + 1;
            const float* ha = g_h + (size_t)nA * H;
            const float* hb = g_h + (size_t)nB * H;
            #pragma unroll
            for (int g = 0; g < 4; g++) {
                int k = lane + 32 * g;
                hs_w[q * H + k] = make_float2(ha[k], hb[k]);
            }
        }
        __syncwarp();

        unsigned long long acc[2][4];
        #pragma unroll
        for (int q = 0; q < 2; q++)
            #pragma unroll
            for (int g = 0; g < 4; g++) acc[q][g] = bia[g];

        #pragma unroll 4
        for (int k = 0; k < H; k++) {
            const float* wr = lws + k * H;
            unsigned long long d0 = dup2(wr[lane]);
            unsigned long long d1 = dup2(wr[lane + 32]);
            unsigned long long d2 = dup2(wr[lane + 64]);
            unsigned long long d3 = dup2(wr[lane + 96]);
            #pragma unroll
            for (int q = 0; q < 2; q++) {
                F2U hv; hv.f = hs_w[q * H + k];
                acc[q][0] = ffma2(hv.u, d0, acc[q][0]);
                acc[q][1] = ffma2(hv.u, d1, acc[q][1]);
                acc[q][2] = ffma2(hv.u, d2, acc[q][2]);
                acc[q][3] = ffma2(hv.u, d3, acc[q][3]);
            }
        }

        #pragma unroll
        for (int q = 0; q < 2; q++) {
            int nA = n0 + 2 * q, nB = nA + 1;
            float* oa = g_xl + (size_t)nA * H;
            float* ob = g_xl + (size_t)nB * H;
            #pragma unroll
            for (int g = 0; g < 4; g++) {
                F2U u; u.u = acc[q][g];
                oa[lane + 32 * g] = u.f.x;
                ob[lane + 32 * g] = u.f.y;
            }
        }
        __syncwarp();
    }
}

// ---------------- build filter table, 4 grid points per warp iter (f32x2 pairs) ----------------
// channels per lane: (2l, 2l+1, 64+2l, 65+2l)
__global__ __launch_bounds__(512, 1) void k_ftab(
        const float* __restrict__ fw1, const float* __restrict__ fb1,
        const float* __restrict__ fw2, const float* __restrict__ fb2) {
    extern __shared__ float s[];
    float* fw1s = s;                                 // 6400
    float* fw2s = fw1s + NRBF * H;                   // 16384
    float* fb1s = fw2s + H * H;                      // 128
    float* fb2s = fb1s + H;                          // 128
    float2* rbfp = (float2*)(fb2s + H);              // 16 warps * 2 pairs * NRBF
    float2* h1p  = rbfp + 16 * 2 * NRBF;             // 16 warps * 2 pairs * H

    int tid = threadIdx.x;
    for (int i = tid; i < NRBF * H / 4; i += blockDim.x)
        ((float4*)fw1s)[i] = ((const float4*)fw1)[i];
    for (int i = tid; i < H * H / 4; i += blockDim.x)
        ((float4*)fw2s)[i] = ((const float4*)fw2)[i];
    if (tid < H) { fb1s[tid] = fb1[tid]; fb2s[tid] = fb2[tid]; }
    __syncthreads();

    int warp = tid >> 5, lane = tid & 31;
    float2* my_rbf = rbfp + warp * 2 * NRBF;
    float2* my_h1  = h1p  + warp * 2 * H;
    int gw = blockIdx.x * (blockDim.x >> 5) + warp;
    int nwarps = gridDim.x * (blockDim.x >> 5);

    float2 b1a = ((const float2*)fb1s)[lane];
    float2 b1b = ((const float2*)(fb1s + 64))[lane];
    float2 b2a = ((const float2*)fb2s)[lane];
    float2 b2b = ((const float2*)(fb2s + 64))[lane];
    unsigned long long bi1[4] = { dup2(b1a.x), dup2(b1a.y), dup2(b1b.x), dup2(b1b.y) };
    unsigned long long bi2[4] = { dup2(b2a.x), dup2(b2a.y), dup2(b2b.x), dup2(b2b.y) };

    for (int t0 = gw * 4; t0 < T_TAB; t0 += nwarps * 4) {   // T_TAB % 4 == 0
        // ---- RBF for 2 pairs ----
        #pragma unroll
        for (int p = 0; p < 2; p++) {
            float d0 = (float)(t0 + 2 * p)     * TAB_STEP;
            float d1 = (float)(t0 + 2 * p + 1) * TAB_STEP;
            if (lane < NRBF) {
                float o = (float)lane * RBF_STEP;
                float u0 = d0 - o, u1 = d1 - o;
                my_rbf[p * NRBF + lane] =
                    make_float2(__expf(RBF_COEFF * u0 * u0), __expf(RBF_COEFF * u1 * u1));
            }
            int r2 = lane + 32;
            if (r2 < NRBF) {
                float o = (float)r2 * RBF_STEP;
                float u0 = d0 - o, u1 = d1 - o;
                my_rbf[p * NRBF + r2] =
                    make_float2(__expf(RBF_COEFF * u0 * u0), __expf(RBF_COEFF * u1 * u1));
            }
        }
        __syncwarp();

        // ---- GEMV1 ----
        unsigned long long acc[2][4];
        #pragma unroll
        for (int p = 0; p < 2; p++)
            #pragma unroll
            for (int g = 0; g < 4; g++) acc[p][g] = bi1[g];

        #pragma unroll 2
        for (int r = 0; r < NRBF; r++) {
            float2 wa = ((const float2*)(fw1s + r * H))[lane];
            float2 wb = ((const float2*)(fw1s + r * H + 64))[lane];
            unsigned long long d0 = dup2(wa.x), d1 = dup2(wa.y);
            unsigned long long d2 = dup2(wb.x), d3 = dup2(wb.y);
            #pragma unroll
            for (int p = 0; p < 2; p++) {
                F2U rb; rb.f = my_rbf[p * NRBF + r];
                acc[p][0] = ffma2(rb.u, d0, acc[p][0]);
                acc[p][1] = ffma2(rb.u, d1, acc[p][1]);
                acc[p][2] = ffma2(rb.u, d2, acc[p][2]);
                acc[p][3] = ffma2(rb.u, d3, acc[p][3]);
            }
        }
        #pragma unroll
        for (int p = 0; p < 2; p++) {
            F2U u0, u1, u2, u3;
            u0.u = acc[p][0]; u1.u = acc[p][1]; u2.u = acc[p][2]; u3.u = acc[p][3];
            u0.f.x = fmaxf(u0.f.x, 0.f); u0.f.y = fmaxf(u0.f.y, 0.f);
            u1.f.x = fmaxf(u1.f.x, 0.f); u1.f.y = fmaxf(u1.f.y, 0.f);
            u2.f.x = fmaxf(u2.f.x, 0.f); u2.f.y = fmaxf(u2.f.y, 0.f);
            u3.f.x = fmaxf(u3.f.x, 0.f); u3.f.y = fmaxf(u3.f.y, 0.f);
            my_h1[p * H + 2 * lane]      = u0.f;
            my_h1[p * H + 2 * lane + 1]  = u1.f;
            my_h1[p * H + 64 + 2 * lane] = u2.f;
            my_h1[p * H + 65 + 2 * lane] = u3.f;
        }
        __syncwarp();

        // ---- GEMV2 ----
        #pragma unroll
        for (int p = 0; p < 2; p++)
            #pragma unroll
            for (int g = 0; g < 4; g++) acc[p][g] = bi2[g];

        #pragma unroll 4
        for (int j = 0; j < H; j++) {
            float2 wa = ((const float2*)(fw2s + j * H))[lane];
            float2 wb = ((const float2*)(fw2s + j * H + 64))[lane];
            unsigned long long d0 = dup2(wa.x), d1 = dup2(wa.y);
            unsigned long long d2 = dup2(wb.x), d3 = dup2(wb.y);
            #pragma unroll
            for (int p = 0; p < 2; p++) {
                F2U hv; hv.f = my_h1[p * H + j];
                acc[p][0] = ffma2(hv.u, d0, acc[p][0]);
                acc[p][1] = ffma2(hv.u, d1, acc[p][1]);
                acc[p][2] = ffma2(hv.u, d2, acc[p][2]);
                acc[p][3] = ffma2(hv.u, d3, acc[p][3]);
            }
        }

        // ---- store 4 table rows ----
        #pragma unroll
        for (int p = 0; p < 2; p++) {
            F2U a0, a1, a2, a3;
            a0.u = acc[p][0]; a1.u = acc[p][1]; a2.u = acc[p][2]; a3.u = acc[p][3];
            float* o0 = g_tab + (size_t)(t0 + 2 * p) * H;
            float* o1 = o0 + H;
            ((float2*)o0)[lane]        = make_float2(a0.f.x, a1.f.x);
            ((float2*)(o0 + 64))[lane] = make_float2(a2.f.x, a3.f.x);
            ((float2*)o1)[lane]        = make_float2(a0.f.y, a1.f.y);
            ((float2*)(o1 + 64))[lane] = make_float2(a2.f.y, a3.f.y);
        }
        __syncwarp();
    }
}

// ---------------- message kernel: msg = xl[col] * lerp(tab, d); red into agg[row] ----------------
#define MEPW 4
__global__ __launch_bounds__(256, 5) void k_msg(const int* __restrict__ erow,
                                                const int* __restrict__ ecol,
                                                const float* __restrict__ eattr) {
    int tid = threadIdx.x;
    int warp = tid >> 5, lane = tid & 31;
    int gw = blockIdx.x * (blockDim.x >> 5) + warp;
    int nwarps = gridDim.x * (blockDim.x >> 5);
    const float4* tab4 = (const float4*)g_tab;
    const float4* xl4  = (const float4*)g_xl;

    for (int e0 = gw * MEPW; e0 < NE; e0 += nwarps * MEPW) {   // NE % MEPW == 0
        float4 w0[MEPW], w1[MEPW], xv[MEPW];
        int rn[MEPW];
        float tt[MEPW];
        #pragma unroll
        for (int t = 0; t < MEPW; t++) {
            int e = e0 + t;
            float f = __ldg(eattr + e) * TAB_INV;
            int i = (int)f;
            if (i > T_TAB - 2) i = T_TAB - 2;
            tt[t] = f - (float)i;
            int cn = __ldg(ecol + e);
            rn[t] = __ldg(erow + e);
            w0[t] = tab4[(size_t)i * 32 + lane];
            w1[t] = tab4[(size_t)i * 32 + 32 + lane];
            xv[t] = xl4[(size_t)cn * 32 + lane];
        }
        #pragma unroll
        for (int t = 0; t < MEPW; t++) {
            float u = tt[t];
            float wx = fmaf(u, w1[t].x - w0[t].x, w0[t].x);
            float wy = fmaf(u, w1[t].y - w0[t].y, w0[t].y);
            float wz = fmaf(u, w1[t].z - w0[t].z, w0[t].z);
            float ww = fmaf(u, w1[t].w - w0[t].w, w0[t].w);
            float* op = g_agg + (size_t)rn[t] * H + 4 * lane;
            red2(op,     xv[t].x * wx, xv[t].y * wy);
            red2(op + 2, xv[t].z * wz, xv[t].w * ww);
        }
    }
}

// ---------------- LayerNorm(h + agg), zero agg; optional fused mean-pool accumulate ----------------
__global__ void k_ln(const float* __restrict__ gam, const float* __restrict__ bet,
                     const int* __restrict__ batch) {
    int gid = blockIdx.x * blockDim.x + threadIdx.x;
    int node = gid >> 5, lane = gid & 31;
    if (node >= NN) return;
    size_t base = (size_t)node * H;
    float v[4];
    #pragma unroll
    for (int c = 0; c < 4; c++) {
        int k = lane + 32 * c;
        v[c] = g_h[base + k] + g_agg[base + k];
    }
    float sum = v[0] + v[1] + v[2] + v[3];
    #pragma unroll
    for (int o = 16; o > 0; o >>= 1) sum += __shfl_xor_sync(0xffffffffu, sum, o);
    float mu = sum * (1.f / H);
    float vs = 0.f;
    #pragma unroll
    for (int c = 0; c < 4; c++) { float d = v[c] - mu; vs += d * d; }
    #pragma unroll
    for (int o = 16; o > 0; o >>= 1) vs += __shfl_xor_sync(0xffffffffu, vs, o);
    float rs = rsqrtf(vs * (1.f / H) + LN_EPS);
    if (batch == nullptr) {
        #pragma unroll
        for (int c = 0; c < 4; c++) {
            int k = lane + 32 * c;
            g_h[base + k] = (v[c] - mu) * rs * gam[k] + bet[k];
            g_agg[base + k] = 0.f;
        }
    } else {
        int bg = batch[node];
        #pragma unroll
        for (int c = 0; c < 4; c++) {
            int k = lane + 32 * c;
            float hv = (v[c] - mu) * rs * gam[k] + bet[k];
            atomicAdd(&g_pool[bg * H + k], hv);
        }
        if (lane == 0) atomicAdd(&g_cnt[bg], 1.f);
    }
}

__global__ void k_div(float* __restrict__ out) {
    int i = blockIdx.x * blockDim.x + threadIdx.x;
    if (i < NG * H) out[i] = g_pool[i] / fmaxf(g_cnt[i / H], 1.f);
}

// ---------------- launch ----------------
extern "C" void kernel_launch(void* const* d_in, const int* in_sizes, int n_in,
                              void* d_out, int out_size) {
    const int*   x     = (const int*)d_in[0];
    const int*   ei    = (const int*)d_in[1];
    const float* ea    = (const float*)d_in[2];
    const int*   batch = (const int*)d_in[3];
    const float* emb   = (const float*)d_in[4];
    const float* fw1   = (const float*)d_in[5];
    const float* fb1   = (const float*)d_in[6];
    const float* fw2   = (const float*)d_in[7];
    const float* fb2   = (const float*)d_in[8];
    const float* lw    = (const float*)d_in[9];
    const float* lb    = (const float*)d_in[10];
    const float* lng   = (const float*)d_in[11];
    const float* lnb   = (const float*)d_in[12];
    float* out = (float*)d_out;

    const int XL_SMEM = (H * H + H) * sizeof(float) + 8 * 2 * H * sizeof(float2); // ~82 KB
    const int FT_SMEM = (NRBF * H + H * H + 2 * H) * sizeof(float)
                      + 16 * 2 * NRBF * sizeof(float2)
                      + 16 * 2 * H * sizeof(float2);                              // ~138 KB
    cudaFuncSetAttribute(k_xl,   cudaFuncAttributeMaxDynamicSharedMemorySize, XL_SMEM);
    cudaFuncSetAttribute(k_ftab, cudaFuncAttributeMaxDynamicSharedMemorySize, FT_SMEM);

    int node_blocks = (NN * 32 + 255) / 256;

    k_init<<<node_blocks, 256>>>(x, emb);
    for (int i = 0; i < NL; i++) {
        k_xl<<<296, 256, XL_SMEM>>>(lw + (size_t)i * H * H, lb + (size_t)i * H);
        k_ftab<<<148, 512, FT_SMEM>>>(fw1 + (size_t)i * NRBF * H, fb1 + (size_t)i * H,
                                      fw2 + (size_t)i * H * H,    fb2 + (size_t)i * H);
        k_msg<<<740, 256>>>(ei, ei + NE, ea);
        k_ln<<<node_blocks, 256>>>(lng + (size_t)i * H, lnb + (size_t)i * H,
                                   (i == NL - 1) ? batch : nullptr);
    }
    k_div<<<(NG * H + 255) / 256, 256>>>(out);
}